// round 9
// baseline (speedup 1.0000x reference)
#include <cuda_runtime.h>
#include <cuda.h>
#include <float.h>
#include <stdint.h>

// STCA loss — fused kernel, bitmask spike scan, warp-autonomous TMA ring.
//  1024 blocks x 128 threads, single wave (24KB smem -> 7 blocks/SM).
//  Block owns 32 traces; warp w scans chunk w (512 steps) of all 32 traces,
//  thread = (chunk = tid>>5, trace = tid&31).
//  Loads: per warp-tile ONE 2D TMA (box 16 steps x 32 traces, SW64) into a
//  3-deep smem ring with per-(warp,buf) mbarriers — replaces 16.8M cp.asyncs
//  (whose 4cyc LSU issue cost was the measured 54us wall) with 131K TMAs.
//  Per 16-step tile: sign mask via PRMT + magic multiply, iterate set bits (~7%).
//  vmax lazily recomputed only for spikeless chunks (P ~ 4e-16).
//  FIX vs r8: driver typedef name is CUtensorMapFloatOOBfill.
// Output: d_out[0] = loss, d_out[1 + trace] = num_clusters as float.

#define B_DIM 128
#define N_DIM 256
#define T_DIM 2048
#define C_GAP 3
#define NTRACE (B_DIM * N_DIM)        // 32768

#define S_CHUNKS 4
#define CHUNK_T  (T_DIM / S_CHUNKS)   // 512
#define TR_PB    32                   // traces per block
#define TPB      (TR_PB * S_CHUNKS)   // 128 threads
#define TT       16                   // timesteps per tile (box inner dim)
#define NTILE    (CHUNK_T / TT)       // 32
#define NBUF     3
#define WBUF_BYTES (TR_PB * TT * 4)   // 2048 B per warp-buf
#define SMEM_FLOATS (S_CHUNKS * NBUF * TR_PB * TT)   // 6144 floats = 24KB
#define NBLOCKS  (NTRACE / TR_PB)     // 1024

#define SENT (1 << 30)

__device__ float        g_partial[NBLOCKS];
__device__ unsigned int g_count;      // zero-init; reset each replay by last block

__device__ __forceinline__ uint32_t smem_u32(const void* p) {
    return (uint32_t)__cvta_generic_to_shared(p);
}
__device__ __forceinline__ void mbar_init(uint32_t a, uint32_t cnt) {
    asm volatile("mbarrier.init.shared.b64 [%0], %1;" :: "r"(a), "r"(cnt) : "memory");
}
__device__ __forceinline__ void mbar_expect_tx(uint32_t a, uint32_t bytes) {
    asm volatile("mbarrier.arrive.expect_tx.shared.b64 _, [%0], %1;" :: "r"(a), "r"(bytes) : "memory");
}
__device__ __forceinline__ void mbar_wait(uint32_t a, uint32_t parity) {
    uint32_t done = 0;
    while (!done) {
        asm volatile(
            "{\n\t.reg .pred p;\n\t"
            "mbarrier.try_wait.parity.acquire.cta.shared::cta.b64 p, [%1], %2, 0x989680;\n\t"
            "selp.b32 %0, 1, 0, p;\n\t}"
            : "=r"(done) : "r"(a), "r"(parity) : "memory");
    }
}
__device__ __forceinline__ void tma_load_2d(uint32_t dst, const CUtensorMap* map,
                                            int x, int y, uint32_t mbar) {
    asm volatile(
        "cp.async.bulk.tensor.2d.shared::cta.global.tile.mbarrier::complete_tx::bytes "
        "[%0], [%1, {%2, %3}], [%4];"
        :: "r"(dst), "l"(map), "r"(x), "r"(y), "r"(mbar) : "memory");
}

__global__ void __launch_bounds__(TPB)
stca_fused(const __grid_constant__ CUtensorMap tmap,
           const float* __restrict__ vmem,
           const int*   __restrict__ labels,
           float*       __restrict__ out)
{
    __shared__ __align__(1024) float sm[SMEM_FLOATS];   // [warp][buf] 2KB blocks
    __shared__ __align__(8) unsigned long long mbar_s[S_CHUNKS * NBUF];
    __shared__ bool amLast;

    const int tid       = threadIdx.x;
    const int traceBase = blockIdx.x * TR_PB;
    const int c         = tid >> 5;        // chunk = warp id
    const int wid       = tid >> 5;
    const int lane      = tid & 31;

    // mbarrier init (count=1: the expect_tx arrive), then block fence
    if (tid < S_CHUNKS * NBUF) mbar_init(smem_u32(&mbar_s[tid]), 1);
    __syncthreads();

    const uint32_t wbuf0 = smem_u32(sm) + wid * NBUF * WBUF_BYTES;
    const int x0 = wid * CHUNK_T;          // column base for this warp's chunk

    // prologue: tiles 0,1,2 in flight
    if (lane == 0) {
        #pragma unroll
        for (int p = 0; p < NBUF; p++) {
            const uint32_t mb = smem_u32(&mbar_s[wid * NBUF + p]);
            mbar_expect_tx(mb, WBUF_BYTES);
            tma_load_2d(wbuf0 + p * WBUF_BYTES, &tmap, x0 + p * TT, traceBase, mb);
        }
    }

    // ---- scan state ----
    int   last = -1000000;                 // chunk-local time of previous spike
    int   k = 0, ft = -1;
    int   curc = 0, curpc = 0;  float cursum = 0.0f;
    int   Fc = 0,   Fp = 0;     float Fs = 0.0f;
    int   Ic = SENT, Ip = 0;    float Is = 0.0f;

    const int sw = (lane >> 1) & 3;        // SW64 slot xor for my row
    int buf = 0;
    uint32_t phases = 0;                   // bit b = pending parity of buf b

    #pragma unroll 1
    for (int tile = 0; tile < NTILE; tile++) {
        const uint32_t mb = smem_u32(&mbar_s[wid * NBUF + buf]);
        mbar_wait(mb, (phases >> buf) & 1);
        phases ^= 1u << buf;

        // my row: 64B at row `lane` of this warp-buf (SW64 swizzled)
        const char* rowbase = (const char*)sm
            + (size_t)(wid * NBUF + buf) * WBUF_BYTES + lane * (TT * 4);

        // 16-bit spike mask from sign bits: PRMT pack + magic multiply.
        uint32_t nm = 0;
        #pragma unroll
        for (int j = 0; j < 4; j++) {
            const uint4 u = *reinterpret_cast<const uint4*>(rowbase + 16 * (j ^ sw));
            uint32_t t0 = __byte_perm(u.x, u.y, 0x0073);
            uint32_t t1 = __byte_perm(u.z, u.w, 0x0073);
            uint32_t sb = __byte_perm(t0, t1, 0x5410);
            sb &= 0x80808080u;
            const uint32_t nib = (sb * 0x00204081u) >> 28;
            nm |= nib << (4 * j);
        }
        uint32_t m = (~nm) & 0xFFFFu;      // spike mask (v >= 0)

        if (m) {
            const int wb = tile * TT;
            if (ft < 0) ft = wb + __ffs(m) - 1;
            do {
                const int i = __ffs(m) - 1;
                m &= m - 1;
                const float v = *reinterpret_cast<const float*>(
                    rowbase + 16 * ((i >> 2) ^ sw) + 4 * (i & 3));
                const int  tg = wb + i;
                const bool nw = (tg - last) > C_GAP;
                const bool cF = nw && (k == 1);
                const bool cI = nw && (k >= 2) && (curc < Ic);
                Fc = cF ? curc : Fc;  Fs = cF ? cursum : Fs;  Fp = cF ? curpc : Fp;
                Ic = cI ? curc : Ic;  Is = cI ? cursum : Is;  Ip = cI ? curpc : Ip;
                k += nw;
                curc   = (nw ? 0 : curc) + 1;
                cursum = (nw ? 0.0f : cursum) + v;
                curpc  = (nw ? 0 : curpc) + (v > 0.0f ? 1 : 0);
                last = tg;
            } while (m);
        }

        // refill this buf with tile+NBUF (warp converged: all lanes' reads issued)
        if (tile + NBUF < NTILE && lane == 0) {
            mbar_expect_tx(mb, WBUF_BYTES);
            tma_load_2d(wbuf0 + buf * WBUF_BYTES, &tmap,
                        x0 + (tile + NBUF) * TT, traceBase, mb);
        }
        buf = (buf == NBUF - 1) ? 0 : buf + 1;
    }

    if (k == 1) { Fc = curc; Fs = cursum; Fp = curpc; }

    // Lazy vmax: only when the chunk has NO spikes (P ~ 4e-16). Rescan gmem.
    float vmax = -FLT_MAX;
    if (k == 0) {
        const float* g = vmem + (size_t)(traceBase + (tid & 31)) * T_DIM + c * CHUNK_T;
        #pragma unroll 1
        for (int j = 0; j < CHUNK_T; j++) vmax = fmaxf(vmax, g[j]);
    }

    // ---- chunk summaries to smem: [128][16] (block barrier; reuse ring area) ----
    __syncthreads();
    float* summ = sm;
    {
        float* w = summ + tid * 16;
        w[0]  = vmax;
        w[1]  = (float)(ft < 0 ? -1 : c * CHUNK_T + ft);
        w[2]  = (float)(c * CHUNK_T + last);
        w[3]  = (float)k;
        w[4]  = (float)Fc;   w[5]  = Fs;     w[6]  = (float)Fp;
        w[7]  = (float)Ic;   w[8]  = Is;     w[9]  = (float)Ip;
        w[10] = (float)curc; w[11] = cursum; w[12] = (float)curpc;
    }
    __syncthreads();

    // ---- merge 4 chunk summaries per trace (threads 0..31) ----
    float* red = sm + TPB * 16;
    float contrib = 0.0f;
    if (tid < TR_PB) {
        float vx = -FLT_MAX;
        int last_t = -1000000, nclust = 0;
        int   opc = -1, opp = 0;  float ops = 0.0f;            // open cluster
        int   bc = SENT, bp = 0;  float bs = 0.0f;             // best closed
        #pragma unroll
        for (int cc = 0; cc < S_CHUNKS; cc++) {
            const float* w = summ + (cc * TR_PB + tid) * 16;
            vx = fmaxf(vx, w[0]);
            const int kk = (int)w[3];
            if (kk == 0) continue;
            const int ftc = (int)w[1], ltc = (int)w[2];
            const int fC = (int)w[4], fP = (int)w[6];
            const int iC = (int)w[7], iP = (int)w[9];
            const int lC = (int)w[10], lP = (int)w[12];
            const float fS = w[5], iS = w[8], lS = w[11];

            if (opc >= 0 && (ftc - last_t) <= C_GAP) {
                const int   mc = opc + fC;
                const float ms = ops + fS;
                const int   mp = opp + fP;
                if (kk == 1) { opc = mc; ops = ms; opp = mp; }
                else {
                    if (mc < bc) { bc = mc; bs = ms; bp = mp; }
                    if (iC < bc) { bc = iC; bs = iS; bp = iP; }
                    opc = lC; ops = lS; opp = lP;
                    nclust += kk - 1;
                }
            } else {
                if (opc >= 0 && opc < bc) { bc = opc; bs = ops; bp = opp; }
                nclust += kk;
                if (kk == 1) { opc = fC; ops = fS; opp = fP; }
                else {
                    if (fC < bc) { bc = fC; bs = fS; bp = fP; }
                    if (iC < bc) { bc = iC; bs = iS; bp = iP; }
                    opc = lC; ops = lS; opp = lP;
                }
            }
            last_t = ltc;
        }
        if (opc >= 0 && opc < bc) { bc = opc; bs = ops; bp = opp; }

        const int trace = traceBase + tid;
        out[1 + trace] = (float)nclust;

        const int b = trace / N_DIM;
        const int n = trace - b * N_DIM;
        if (n == labels[b]) {
            if (nclust == 0) contrib = -vx;
        } else if (nclust > 0) {
            contrib = bs / fmaxf((float)bp, 1.0f);
        }
    }

    // ---- block tree reduction (128 threads; >=32 contribute 0) ----
    red[tid] = contrib;
    __syncthreads();
    #pragma unroll
    for (int off = TPB / 2; off > 0; off >>= 1) {
        if (tid < off) red[tid] += red[tid + off];
        __syncthreads();
    }
    if (tid == 0) {
        g_partial[blockIdx.x] = red[0];
        __threadfence();
        amLast = (atomicAdd(&g_count, 1u) == (unsigned)(gridDim.x - 1));
    }
    __syncthreads();

    if (amLast) {
        __threadfence();
        float x = 0.0f;
        #pragma unroll
        for (int j = 0; j < NBLOCKS / TPB; j++) x += g_partial[tid + TPB * j];
        red[tid] = x;
        __syncthreads();
        #pragma unroll
        for (int off = TPB / 2; off > 0; off >>= 1) {
            if (tid < off) red[tid] += red[tid + off];
            __syncthreads();
        }
        if (tid == 0) {
            out[0] = red[0];
            g_count = 0;                   // reset for next graph replay
        }
    }
}

// ---- host: build TMA descriptor via runtime-queried driver entry point ----
typedef CUresult (*cuTensorMapEncodeTiled_t)(
    CUtensorMap*, CUtensorMapDataType, cuuint32_t, void*,
    const cuuint64_t*, const cuuint64_t*, const cuuint32_t*, const cuuint32_t*,
    CUtensorMapInterleave, CUtensorMapSwizzle, CUtensorMapL2promotion,
    CUtensorMapFloatOOBfill);

extern "C" void kernel_launch(void* const* d_in, const int* in_sizes, int n_in,
                              void* d_out, int out_size)
{
    const float* vmem   = (const float*)d_in[0];
    // d_in[1] (vlastmem) unused by the forward computation.
    const int*   labels = (const int*)d_in[2];
    float*       out    = (float*)d_out;

    void* fn = nullptr;
    cudaDriverEntryPointQueryResult qr;
    cudaGetDriverEntryPoint("cuTensorMapEncodeTiled", &fn, cudaEnableDefault, &qr);
    cuTensorMapEncodeTiled_t encode = (cuTensorMapEncodeTiled_t)fn;

    CUtensorMap tmap;
    cuuint64_t dims[2]    = {(cuuint64_t)T_DIM, (cuuint64_t)NTRACE};
    cuuint64_t strides[1] = {(cuuint64_t)T_DIM * sizeof(float)};
    cuuint32_t box[2]     = {TT, TR_PB};            // 16 floats (64B) x 32 rows
    cuuint32_t estr[2]    = {1, 1};
    encode(&tmap, CU_TENSOR_MAP_DATA_TYPE_FLOAT32, 2, (void*)vmem,
           dims, strides, box, estr,
           CU_TENSOR_MAP_INTERLEAVE_NONE, CU_TENSOR_MAP_SWIZZLE_64B,
           CU_TENSOR_MAP_L2_PROMOTION_L2_128B, CU_TENSOR_MAP_FLOAT_OOB_FILL_NONE);

    stca_fused<<<NBLOCKS, TPB>>>(tmap, vmem, labels, out);
}

// round 10
// speedup vs baseline: 1.2985x; 1.2985x over previous
#include <cuda_runtime.h>
#include <float.h>
#include <stdint.h>

// STCA loss — fused kernel, bitmask spike scan, lane-private cp.async.bulk ring.
//  1024 blocks x 128 threads (TR_PB=32 traces, S_CHUNKS=4 chunks of 512 steps).
//  Thread (chunk = tid>>5, trace = tid&31) scans 512 steps in 8 tiles of 64.
//  Loads: each LANE issues ONE cp.async.bulk of 256B (its own contiguous
//  row-tile) into its own padded smem row; per-(warp,buf) mbarrier, 32 arrivals
//  + 8KB tx per phase. 1.05M bulk ops replace 16.8M LDGSTS (whose ~4cyc/SMSP
//  issue floor was the r7 53.8us wall). Rows lane-private -> NO sync in hot loop.
//  Per 64-step tile: two 32-bit sign masks via PRMT+magic-mul, iterate set bits.
//  vmax lazily recomputed only for spikeless chunks (P ~ 4e-16).
// Output: d_out[0] = loss, d_out[1 + trace] = num_clusters as float.

#define B_DIM 128
#define N_DIM 256
#define T_DIM 2048
#define C_GAP 3
#define NTRACE (B_DIM * N_DIM)        // 32768

#define S_CHUNKS 4
#define CHUNK_T  (T_DIM / S_CHUNKS)   // 512
#define TR_PB    32                   // traces per block
#define TPB      (TR_PB * S_CHUNKS)   // 128 threads
#define TT       64                   // timesteps per tile (256B per row-tile)
#define NTILE    (CHUNK_T / TT)       // 8
#define ROWB     272                  // row pitch bytes (256 data + 16 pad)
#define NBUF     2
#define WBUF_B   (TR_PB * ROWB)       // 8704 B per warp-buf
#define SMEM_BYTES (S_CHUNKS * NBUF * WBUF_B)   // 69632 B -> 3 blocks/SM
#define NBLOCKS  (NTRACE / TR_PB)     // 1024

#define SENT (1 << 30)

__device__ float        g_partial[NBLOCKS];
__device__ unsigned int g_count;      // zero-init; reset each replay by last block

__device__ __forceinline__ uint32_t smem_u32(const void* p) {
    return (uint32_t)__cvta_generic_to_shared(p);
}
__device__ __forceinline__ void mbar_init(uint32_t a, uint32_t cnt) {
    asm volatile("mbarrier.init.shared.b64 [%0], %1;" :: "r"(a), "r"(cnt) : "memory");
}
__device__ __forceinline__ void mbar_expect_tx(uint32_t a, uint32_t bytes) {
    asm volatile("mbarrier.arrive.expect_tx.shared.b64 _, [%0], %1;" :: "r"(a), "r"(bytes) : "memory");
}
__device__ __forceinline__ void mbar_wait(uint32_t a, uint32_t parity) {
    uint32_t done = 0;
    while (!done) {
        asm volatile(
            "{\n\t.reg .pred p;\n\t"
            "mbarrier.try_wait.parity.acquire.cta.shared::cta.b64 p, [%1], %2, 0x989680;\n\t"
            "selp.b32 %0, 1, 0, p;\n\t}"
            : "=r"(done) : "r"(a), "r"(parity) : "memory");
    }
}
__device__ __forceinline__ void bulk_g2s(uint32_t dst, const void* src,
                                         uint32_t bytes, uint32_t mbar) {
    asm volatile(
        "cp.async.bulk.shared::cta.global.mbarrier::complete_tx::bytes [%0], [%1], %2, [%3];"
        :: "r"(dst), "l"(src), "r"(bytes), "r"(mbar) : "memory");
}

__global__ void __launch_bounds__(TPB)
stca_fused(const float* __restrict__ vmem,
           const int*   __restrict__ labels,
           float*       __restrict__ out)
{
    extern __shared__ float sm[];
    __shared__ __align__(8) unsigned long long mbar_s[S_CHUNKS * NBUF];
    __shared__ bool amLast;

    const int tid       = threadIdx.x;
    const int traceBase = blockIdx.x * TR_PB;
    const int c         = tid >> 5;        // chunk = warp id
    const int wid       = tid >> 5;
    const int lane      = tid & 31;

    // mbarriers: 32 arrivals per phase (each lane does arrive.expect_tx once)
    if (tid < S_CHUNKS * NBUF) mbar_init(smem_u32(&mbar_s[tid]), 32);
    __syncthreads();

    // my gmem row (chunk c of trace lane) and my smem row in each buf
    const char* gsrc = (const char*)(vmem
        + (size_t)(traceBase + lane) * T_DIM + c * CHUNK_T);
    uint32_t sdst[NBUF];
    const float* srow[NBUF];
    #pragma unroll
    for (int p = 0; p < NBUF; p++) {
        const uint32_t off = (wid * NBUF + p) * WBUF_B + lane * ROWB;
        sdst[p] = smem_u32(sm) + off;
        srow[p] = (const float*)((const char*)sm + off);
    }
    uint32_t mb[NBUF];
    #pragma unroll
    for (int p = 0; p < NBUF; p++) mb[p] = smem_u32(&mbar_s[wid * NBUF + p]);

    // prologue: tiles 0,1 in flight
    #pragma unroll
    for (int p = 0; p < NBUF; p++) {
        mbar_expect_tx(mb[p], 256);
        bulk_g2s(sdst[p], gsrc + p * (TT * 4), 256, mb[p]);
    }

    // ---- scan state ----
    int   last = -1000000;                 // chunk-local time of previous spike
    int   k = 0, ft = -1;
    int   curc = 0, curpc = 0;  float cursum = 0.0f;
    int   Fc = 0,   Fp = 0;     float Fs = 0.0f;
    int   Ic = SENT, Ip = 0;    float Is = 0.0f;

    int buf = 0;
    uint32_t phases = 0;                   // bit b = pending parity of buf b

    #pragma unroll 1
    for (int tile = 0; tile < NTILE; tile++) {
        mbar_wait(mb[buf], (phases >> buf) & 1);
        phases ^= 1u << buf;

        const float* r = srow[buf];

        // two 32-bit spike masks over 64 steps: PRMT pack + magic multiply
        uint32_t msk[2];
        #pragma unroll
        for (int h = 0; h < 2; h++) {
            uint32_t nm = 0;
            #pragma unroll
            for (int j = 0; j < 8; j++) {
                const uint4 u = *reinterpret_cast<const uint4*>(r + h * 32 + 4 * j);
                uint32_t t0 = __byte_perm(u.x, u.y, 0x0073);
                uint32_t t1 = __byte_perm(u.z, u.w, 0x0073);
                uint32_t sb = __byte_perm(t0, t1, 0x5410);
                sb &= 0x80808080u;
                nm |= ((sb * 0x00204081u) >> 28) << (4 * j);
            }
            msk[h] = ~nm;                  // spike bits (v >= 0)
        }

        #pragma unroll
        for (int h = 0; h < 2; h++) {
            uint32_t m = msk[h];
            if (m) {
                const int wb = tile * TT + h * 32;
                if (ft < 0) ft = wb + __ffs(m) - 1;
                do {
                    const int i = __ffs(m) - 1;
                    m &= m - 1;
                    const float v = r[h * 32 + i];      // v >= 0 guaranteed
                    const int  tg = wb + i;
                    const bool nw = (tg - last) > C_GAP;
                    const bool cF = nw && (k == 1);
                    const bool cI = nw && (k >= 2) && (curc < Ic);
                    Fc = cF ? curc : Fc;  Fs = cF ? cursum : Fs;  Fp = cF ? curpc : Fp;
                    Ic = cI ? curc : Ic;  Is = cI ? cursum : Is;  Ip = cI ? curpc : Ip;
                    k += nw;
                    curc   = (nw ? 0 : curc) + 1;
                    cursum = (nw ? 0.0f : cursum) + v;
                    curpc  = (nw ? 0 : curpc) + (v > 0.0f ? 1 : 0);
                    last = tg;
                } while (m);
            }
        }

        // refill my (lane-private) row of this buf with tile+NBUF
        if (tile + NBUF < NTILE) {
            mbar_expect_tx(mb[buf], 256);
            bulk_g2s(sdst[buf], gsrc + (tile + NBUF) * (TT * 4), 256, mb[buf]);
        }
        buf ^= 1;
    }

    if (k == 1) { Fc = curc; Fs = cursum; Fp = curpc; }

    // Lazy vmax: only when the chunk has NO spikes (P ~ 4e-16). Rescan gmem.
    float vmax = -FLT_MAX;
    if (k == 0) {
        const float* g = (const float*)gsrc;
        #pragma unroll 1
        for (int j = 0; j < CHUNK_T; j++) vmax = fmaxf(vmax, g[j]);
    }

    // ---- chunk summaries to smem: [128][16] (block barrier; reuse ring area) ----
    __syncthreads();
    float* summ = sm;
    {
        float* w = summ + tid * 16;
        w[0]  = vmax;
        w[1]  = (float)(ft < 0 ? -1 : c * CHUNK_T + ft);
        w[2]  = (float)(c * CHUNK_T + last);
        w[3]  = (float)k;
        w[4]  = (float)Fc;   w[5]  = Fs;     w[6]  = (float)Fp;
        w[7]  = (float)Ic;   w[8]  = Is;     w[9]  = (float)Ip;
        w[10] = (float)curc; w[11] = cursum; w[12] = (float)curpc;
    }
    __syncthreads();

    // ---- merge 4 chunk summaries per trace (threads 0..31) ----
    float* red = sm + TPB * 16;
    float contrib = 0.0f;
    if (tid < TR_PB) {
        float vx = -FLT_MAX;
        int last_t = -1000000, nclust = 0;
        int   opc = -1, opp = 0;  float ops = 0.0f;            // open cluster
        int   bc = SENT, bp = 0;  float bs = 0.0f;             // best closed
        #pragma unroll
        for (int cc = 0; cc < S_CHUNKS; cc++) {
            const float* w = summ + (cc * TR_PB + tid) * 16;
            vx = fmaxf(vx, w[0]);
            const int kk = (int)w[3];
            if (kk == 0) continue;
            const int ftc = (int)w[1], ltc = (int)w[2];
            const int fC = (int)w[4], fP = (int)w[6];
            const int iC = (int)w[7], iP = (int)w[9];
            const int lC = (int)w[10], lP = (int)w[12];
            const float fS = w[5], iS = w[8], lS = w[11];

            if (opc >= 0 && (ftc - last_t) <= C_GAP) {
                const int   mc = opc + fC;
                const float ms = ops + fS;
                const int   mp = opp + fP;
                if (kk == 1) { opc = mc; ops = ms; opp = mp; }
                else {
                    if (mc < bc) { bc = mc; bs = ms; bp = mp; }
                    if (iC < bc) { bc = iC; bs = iS; bp = iP; }
                    opc = lC; ops = lS; opp = lP;
                    nclust += kk - 1;
                }
            } else {
                if (opc >= 0 && opc < bc) { bc = opc; bs = ops; bp = opp; }
                nclust += kk;
                if (kk == 1) { opc = fC; ops = fS; opp = fP; }
                else {
                    if (fC < bc) { bc = fC; bs = fS; bp = fP; }
                    if (iC < bc) { bc = iC; bs = iS; bp = iP; }
                    opc = lC; ops = lS; opp = lP;
                }
            }
            last_t = ltc;
        }
        if (opc >= 0 && opc < bc) { bc = opc; bs = ops; bp = opp; }

        const int trace = traceBase + tid;
        out[1 + trace] = (float)nclust;

        const int b = trace / N_DIM;
        const int n = trace - b * N_DIM;
        if (n == labels[b]) {
            if (nclust == 0) contrib = -vx;
        } else if (nclust > 0) {
            contrib = bs / fmaxf((float)bp, 1.0f);
        }
    }

    // ---- block tree reduction (128 threads; >=32 contribute 0) ----
    red[tid] = contrib;
    __syncthreads();
    #pragma unroll
    for (int off = TPB / 2; off > 0; off >>= 1) {
        if (tid < off) red[tid] += red[tid + off];
        __syncthreads();
    }
    if (tid == 0) {
        g_partial[blockIdx.x] = red[0];
        __threadfence();
        amLast = (atomicAdd(&g_count, 1u) == (unsigned)(gridDim.x - 1));
    }
    __syncthreads();

    if (amLast) {
        __threadfence();
        float x = 0.0f;
        #pragma unroll
        for (int j = 0; j < NBLOCKS / TPB; j++) x += g_partial[tid + TPB * j];
        red[tid] = x;
        __syncthreads();
        #pragma unroll
        for (int off = TPB / 2; off > 0; off >>= 1) {
            if (tid < off) red[tid] += red[tid + off];
            __syncthreads();
        }
        if (tid == 0) {
            out[0] = red[0];
            g_count = 0;                   // reset for next graph replay
        }
    }
}

extern "C" void kernel_launch(void* const* d_in, const int* in_sizes, int n_in,
                              void* d_out, int out_size)
{
    const float* vmem   = (const float*)d_in[0];
    // d_in[1] (vlastmem) unused by the forward computation.
    const int*   labels = (const int*)d_in[2];
    float*       out    = (float*)d_out;

    cudaFuncSetAttribute(stca_fused, cudaFuncAttributeMaxDynamicSharedMemorySize, SMEM_BYTES);
    stca_fused<<<NBLOCKS, TPB, SMEM_BYTES>>>(vmem, labels, out);
}

// round 11
// speedup vs baseline: 1.4247x; 1.0972x over previous
#include <cuda_runtime.h>
#include <float.h>
#include <stdint.h>

// STCA loss — fused kernel, bitmask spike scan, warp-autonomous LDGSTS ring.
//  r11: occupancy push. S_CHUNKS=8 (chunk=256), TR_PB=16 -> 2048 blocks x 128
//  threads = 8192 warps (48/SM resident; r7 supplied only 27.7/SM and warps/SM
//  has been the monotone perf lever: 12w->70us, 24w->66us, 28w->54us).
//  Thread (chunk = tid>>4, trace = tid&15) scans 256 steps in 32 tiles of 8.
//  Warp w stages rows 32w..32w+31 via cp.async (2 x 16B per lane per tile),
//  3-deep ring, __syncwarp only. PITCH=12 floats (48B rows): LDS.128 conflict-
//  free (slot = 3*lane mod 8). Spike monoid on set bits only (~7% density).
//  vmax lazily recomputed only for spikeless chunks.
// Output: d_out[0] = loss, d_out[1 + trace] = num_clusters as float.

#define B_DIM 128
#define N_DIM 256
#define T_DIM 2048
#define C_GAP 3
#define NTRACE (B_DIM * N_DIM)        // 32768

#define S_CHUNKS 8
#define CHUNK_T  (T_DIM / S_CHUNKS)   // 256
#define TR_PB    16                   // traces per block
#define TPB      (TR_PB * S_CHUNKS)   // 128 threads
#define TT       8                    // timesteps per tile (32B per row-tile)
#define NTILE    (CHUNK_T / TT)       // 32
#define PITCH    12                   // floats per smem row (48B, conflict-free)
#define TILE_FLOATS (TPB * PITCH)     // 1536
#define TILE_BYTES  (TILE_FLOATS * 4) // 6144
#define NBUF     3                    // 18432 B total -> 11-12 blocks/SM
#define NBLOCKS  (NTRACE / TR_PB)     // 2048

#define SENT (1 << 30)

__device__ float        g_partial[NBLOCKS];
__device__ unsigned int g_count;      // zero-init; reset each replay by last block

__device__ __forceinline__ void cp_async16(uint32_t saddr, const float* gptr) {
    asm volatile("cp.async.cg.shared.global [%0], [%1], 16;\n" :: "r"(saddr), "l"(gptr));
}
__device__ __forceinline__ void cp_commit() { asm volatile("cp.async.commit_group;\n"); }
template <int N>
__device__ __forceinline__ void cp_wait() { asm volatile("cp.async.wait_group %0;\n" :: "n"(N)); }

__global__ void __launch_bounds__(TPB, 12)
stca_fused(const float* __restrict__ vmem,
           const int*   __restrict__ labels,
           float*       __restrict__ out)
{
    __shared__ float sm[NBUF * TILE_FLOATS];
    __shared__ bool  amLast;

    const int tid       = threadIdx.x;
    const int traceBase = blockIdx.x * TR_PB;
    const int c         = tid >> 4;        // chunk 0..7 (row = tid)
    const int wid       = tid >> 5;        // warp stages rows 32w..32w+31
    const int lane      = tid & 31;

    // ---- warp-local cp.async mapping: 2 x 16B per lane per tile ----
    const int tq  = lane & 1;              // 16B half of the 32B row-tile
    const int rl0 = lane >> 1;             // 0..15
    const float* gbase[2];
    uint32_t     sbase[2];
    #pragma unroll
    for (int q = 0; q < 2; q++) {
        const int r   = 32 * wid + rl0 + 16 * q;   // block-local row
        const int rtr = r & 15, rc = r >> 4;
        gbase[q] = vmem + (size_t)(traceBase + rtr) * T_DIM + rc * CHUNK_T + tq * 4;
        sbase[q] = (uint32_t)__cvta_generic_to_shared(sm) + (r * PITCH + tq * 4) * 4;
    }

    // prologue: tiles 0,1,2 in flight
    #pragma unroll
    for (int p = 0; p < NBUF; p++) {
        #pragma unroll
        for (int q = 0; q < 2; q++) cp_async16(sbase[q] + p * TILE_BYTES, gbase[q] + p * TT);
        cp_commit();
    }

    // ---- scan state ----
    int   last = -1000000;                 // chunk-local time of previous spike
    int   k = 0, ft = -1;
    int   curc = 0, curpc = 0;  float cursum = 0.0f;
    int   Fc = 0,   Fp = 0;     float Fs = 0.0f;
    int   Ic = SENT, Ip = 0;    float Is = 0.0f;

    const float* myrow0 = sm + tid * PITCH;
    int buf = 0;

    #pragma unroll 1
    for (int tile = 0; tile < NTILE; tile++) {
        if (tile < NTILE - 2)       cp_wait<2>();
        else if (tile == NTILE - 2) cp_wait<1>();
        else                        cp_wait<0>();
        __syncwarp();                      // producers' smem writes visible warp-wide

        const float* r = myrow0 + buf * TILE_FLOATS;

        // 8-bit spike mask from sign bits: PRMT pack + magic multiply.
        uint32_t nm = 0;
        #pragma unroll
        for (int j = 0; j < 2; j++) {
            const uint4 u = *reinterpret_cast<const uint4*>(r + 4 * j);
            uint32_t t0 = __byte_perm(u.x, u.y, 0x0073);
            uint32_t t1 = __byte_perm(u.z, u.w, 0x0073);
            uint32_t sb = __byte_perm(t0, t1, 0x5410);
            sb &= 0x80808080u;
            nm |= ((sb * 0x00204081u) >> 28) << (4 * j);
        }
        uint32_t m = (~nm) & 0xFFu;        // spike mask (v >= 0)

        if (m) {
            const int wb = tile * TT;
            if (ft < 0) ft = wb + __ffs(m) - 1;
            do {
                const int i = __ffs(m) - 1;
                m &= m - 1;
                const float v = r[i];      // v >= 0 guaranteed
                const int  tg = wb + i;
                const bool nw = (tg - last) > C_GAP;
                const bool cF = nw && (k == 1);
                const bool cI = nw && (k >= 2) && (curc < Ic);
                Fc = cF ? curc : Fc;  Fs = cF ? cursum : Fs;  Fp = cF ? curpc : Fp;
                Ic = cI ? curc : Ic;  Is = cI ? cursum : Is;  Ip = cI ? curpc : Ip;
                k += nw;
                curc   = (nw ? 0 : curc) + 1;
                cursum = (nw ? 0.0f : cursum) + v;
                curpc  = (nw ? 0 : curpc) + (v > 0.0f ? 1 : 0);
                last = tg;
            } while (m);
        }

        __syncwarp();                      // all lanes done reading buf
        if (tile + NBUF < NTILE) {         // refill buf with tile+3
            const uint32_t soff = buf * TILE_BYTES;
            const int goff = (tile + NBUF) * TT;
            #pragma unroll
            for (int q = 0; q < 2; q++) cp_async16(sbase[q] + soff, gbase[q] + goff);
            cp_commit();
        }
        buf = (buf == NBUF - 1) ? 0 : buf + 1;
    }

    if (k == 1) { Fc = curc; Fs = cursum; Fp = curpc; }

    // Lazy vmax: only when the chunk has NO spikes. Rescan gmem.
    float vmax = -FLT_MAX;
    if (k == 0) {
        const float* g = vmem + (size_t)(traceBase + (tid & 15)) * T_DIM + c * CHUNK_T;
        #pragma unroll 1
        for (int j = 0; j < CHUNK_T; j++) vmax = fmaxf(vmax, g[j]);
    }

    // ---- chunk summaries to smem: [128][16] (block barrier; reuse ring area) ----
    __syncthreads();
    float* summ = sm;
    {
        float* w = summ + tid * 16;
        w[0]  = vmax;
        w[1]  = (float)(ft < 0 ? -1 : c * CHUNK_T + ft);
        w[2]  = (float)(c * CHUNK_T + last);
        w[3]  = (float)k;
        w[4]  = (float)Fc;   w[5]  = Fs;     w[6]  = (float)Fp;
        w[7]  = (float)Ic;   w[8]  = Is;     w[9]  = (float)Ip;
        w[10] = (float)curc; w[11] = cursum; w[12] = (float)curpc;
    }
    __syncthreads();

    // ---- merge 8 chunk summaries per trace (threads 0..15) ----
    float* red = sm + TPB * 16;
    float contrib = 0.0f;
    if (tid < TR_PB) {
        float vx = -FLT_MAX;
        int last_t = -1000000, nclust = 0;
        int   opc = -1, opp = 0;  float ops = 0.0f;            // open cluster
        int   bc = SENT, bp = 0;  float bs = 0.0f;             // best closed
        #pragma unroll
        for (int cc = 0; cc < S_CHUNKS; cc++) {
            const float* w = summ + (cc * TR_PB + tid) * 16;
            vx = fmaxf(vx, w[0]);
            const int kk = (int)w[3];
            if (kk == 0) continue;
            const int ftc = (int)w[1], ltc = (int)w[2];
            const int fC = (int)w[4], fP = (int)w[6];
            const int iC = (int)w[7], iP = (int)w[9];
            const int lC = (int)w[10], lP = (int)w[12];
            const float fS = w[5], iS = w[8], lS = w[11];

            if (opc >= 0 && (ftc - last_t) <= C_GAP) {
                const int   mc = opc + fC;
                const float ms = ops + fS;
                const int   mp = opp + fP;
                if (kk == 1) { opc = mc; ops = ms; opp = mp; }
                else {
                    if (mc < bc) { bc = mc; bs = ms; bp = mp; }
                    if (iC < bc) { bc = iC; bs = iS; bp = iP; }
                    opc = lC; ops = lS; opp = lP;
                    nclust += kk - 1;
                }
            } else {
                if (opc >= 0 && opc < bc) { bc = opc; bs = ops; bp = opp; }
                nclust += kk;
                if (kk == 1) { opc = fC; ops = fS; opp = fP; }
                else {
                    if (fC < bc) { bc = fC; bs = fS; bp = fP; }
                    if (iC < bc) { bc = iC; bs = iS; bp = iP; }
                    opc = lC; ops = lS; opp = lP;
                }
            }
            last_t = ltc;
        }
        if (opc >= 0 && opc < bc) { bc = opc; bs = ops; bp = opp; }

        const int trace = traceBase + tid;
        out[1 + trace] = (float)nclust;

        const int b = trace / N_DIM;
        const int n = trace - b * N_DIM;
        if (n == labels[b]) {
            if (nclust == 0) contrib = -vx;
        } else if (nclust > 0) {
            contrib = bs / fmaxf((float)bp, 1.0f);
        }
    }

    // ---- block tree reduction (128 threads; >=16 contribute 0) ----
    red[tid] = contrib;
    __syncthreads();
    #pragma unroll
    for (int off = TPB / 2; off > 0; off >>= 1) {
        if (tid < off) red[tid] += red[tid + off];
        __syncthreads();
    }
    if (tid == 0) {
        g_partial[blockIdx.x] = red[0];
        __threadfence();
        amLast = (atomicAdd(&g_count, 1u) == (unsigned)(gridDim.x - 1));
    }
    __syncthreads();

    if (amLast) {
        __threadfence();
        float x = 0.0f;
        #pragma unroll
        for (int j = 0; j < NBLOCKS / TPB; j++) x += g_partial[tid + TPB * j];
        red[tid] = x;
        __syncthreads();
        #pragma unroll
        for (int off = TPB / 2; off > 0; off >>= 1) {
            if (tid < off) red[tid] += red[tid + off];
            __syncthreads();
        }
        if (tid == 0) {
            out[0] = red[0];
            g_count = 0;                   // reset for next graph replay
        }
    }
}

extern "C" void kernel_launch(void* const* d_in, const int* in_sizes, int n_in,
                              void* d_out, int out_size)
{
    const float* vmem   = (const float*)d_in[0];
    // d_in[1] (vlastmem) unused by the forward computation.
    const int*   labels = (const int*)d_in[2];
    float*       out    = (float*)d_out;

    stca_fused<<<NBLOCKS, TPB>>>(vmem, labels, out);
}

// round 12
// speedup vs baseline: 1.7175x; 1.2055x over previous
#include <cuda_runtime.h>
#include <float.h>
#include <stdint.h>

// STCA loss — fused kernel, bitmask spike scan, warp-autonomous LDGSTS ring.
//  r12: 44 warps/SM at r7's per-byte efficiency. S_CHUNKS=8 (chunk=256),
//  TR_PB=16, TPB=128 -> 2048 blocks; TT=16 (64B rows, 8 lines/instr — the
//  efficient r7 shape; r11's TT=8/32B rows doubled L1 wavefronts and lost),
//  NBUF=2 -> smem 20.5KB -> 11 blocks/SM resident wave-1.
//  Thread (chunk = tid>>4, trace = tid&15) scans 256 steps in 16 tiles of 16.
//  Warp w stages rows 32w..32w+31 via cp.async (4 x 16B per lane per tile),
//  2-deep ring, __syncwarp only. PITCH=20 floats: LDS.128 conflict-free.
//  Spike monoid on set bits only (~7%); vmax lazy for spikeless chunks.
// Output: d_out[0] = loss, d_out[1 + trace] = num_clusters as float.

#define B_DIM 128
#define N_DIM 256
#define T_DIM 2048
#define C_GAP 3
#define NTRACE (B_DIM * N_DIM)        // 32768

#define S_CHUNKS 8
#define CHUNK_T  (T_DIM / S_CHUNKS)   // 256
#define TR_PB    16                   // traces per block
#define TPB      (TR_PB * S_CHUNKS)   // 128 threads
#define TT       16                   // timesteps per tile (64B per row-tile)
#define NTILE    (CHUNK_T / TT)       // 16
#define PITCH    20                   // floats per smem row (80B, conflict-free)
#define TILE_FLOATS (TPB * PITCH)     // 2560
#define TILE_BYTES  (TILE_FLOATS * 4) // 10240
#define NBUF     2                    // 20480 B total -> 11 blocks/SM
#define NBLOCKS  (NTRACE / TR_PB)     // 2048

#define SENT (1 << 30)

__device__ float        g_partial[NBLOCKS];
__device__ unsigned int g_count;      // zero-init; reset each replay by last block

__device__ __forceinline__ void cp_async16(uint32_t saddr, const float* gptr) {
    asm volatile("cp.async.cg.shared.global [%0], [%1], 16;\n" :: "r"(saddr), "l"(gptr));
}
__device__ __forceinline__ void cp_commit() { asm volatile("cp.async.commit_group;\n"); }
template <int N>
__device__ __forceinline__ void cp_wait() { asm volatile("cp.async.wait_group %0;\n" :: "n"(N)); }

__global__ void __launch_bounds__(TPB, 11)
stca_fused(const float* __restrict__ vmem,
           const int*   __restrict__ labels,
           float*       __restrict__ out)
{
    __shared__ float sm[NBUF * TILE_FLOATS];
    __shared__ bool  amLast;

    const int tid       = threadIdx.x;
    const int traceBase = blockIdx.x * TR_PB;
    const int c         = tid >> 4;        // chunk 0..7 (row = tid)
    const int wid       = tid >> 5;        // warp stages rows 32w..32w+31
    const int lane      = tid & 31;

    // ---- warp-local cp.async mapping: 4 x 16B per lane per tile ----
    const int tq  = lane & 3;              // float4 column 0..3 of the 64B row-tile
    const int rl0 = lane >> 2;             // 0..7
    const float* gbase[4];
    uint32_t     sbase[4];
    #pragma unroll
    for (int q = 0; q < 4; q++) {
        const int r   = 32 * wid + rl0 + 8 * q;    // block-local row
        const int rtr = r & 15, rc = r >> 4;
        gbase[q] = vmem + (size_t)(traceBase + rtr) * T_DIM + rc * CHUNK_T + tq * 4;
        sbase[q] = (uint32_t)__cvta_generic_to_shared(sm) + (r * PITCH + tq * 4) * 4;
    }

    // prologue: tiles 0,1 in flight
    #pragma unroll
    for (int p = 0; p < NBUF; p++) {
        #pragma unroll
        for (int q = 0; q < 4; q++) cp_async16(sbase[q] + p * TILE_BYTES, gbase[q] + p * TT);
        cp_commit();
    }

    // ---- scan state ----
    int   last = -1000000;                 // chunk-local time of previous spike
    int   k = 0, ft = -1;
    int   curc = 0, curpc = 0;  float cursum = 0.0f;
    int   Fc = 0,   Fp = 0;     float Fs = 0.0f;
    int   Ic = SENT, Ip = 0;    float Is = 0.0f;

    const float* myrow0 = sm + tid * PITCH;
    int buf = 0;

    #pragma unroll 1
    for (int tile = 0; tile < NTILE; tile++) {
        if (tile < NTILE - 1) cp_wait<1>(); else cp_wait<0>();
        __syncwarp();                      // producers' smem writes visible warp-wide

        const float* r = myrow0 + buf * TILE_FLOATS;

        // 16-bit spike mask from sign bits: PRMT pack + magic multiply.
        uint32_t nm = 0;
        #pragma unroll
        for (int j = 0; j < 4; j++) {
            const uint4 u = *reinterpret_cast<const uint4*>(r + 4 * j);
            uint32_t t0 = __byte_perm(u.x, u.y, 0x0073);
            uint32_t t1 = __byte_perm(u.z, u.w, 0x0073);
            uint32_t sb = __byte_perm(t0, t1, 0x5410);
            sb &= 0x80808080u;
            nm |= ((sb * 0x00204081u) >> 28) << (4 * j);
        }
        uint32_t m = (~nm) & 0xFFFFu;      // spike mask (v >= 0)

        if (m) {
            const int wb = tile * TT;
            if (ft < 0) ft = wb + __ffs(m) - 1;
            do {
                const int i = __ffs(m) - 1;
                m &= m - 1;
                const float v = r[i];      // v >= 0 guaranteed
                const int  tg = wb + i;
                const bool nw = (tg - last) > C_GAP;
                const bool cF = nw && (k == 1);
                const bool cI = nw && (k >= 2) && (curc < Ic);
                Fc = cF ? curc : Fc;  Fs = cF ? cursum : Fs;  Fp = cF ? curpc : Fp;
                Ic = cI ? curc : Ic;  Is = cI ? cursum : Is;  Ip = cI ? curpc : Ip;
                k += nw;
                curc   = (nw ? 0 : curc) + 1;
                cursum = (nw ? 0.0f : cursum) + v;
                curpc  = (nw ? 0 : curpc) + (v > 0.0f ? 1 : 0);
                last = tg;
            } while (m);
        }

        __syncwarp();                      // all lanes done reading buf
        if (tile + NBUF < NTILE) {         // refill buf with tile+2
            const uint32_t soff = buf * TILE_BYTES;
            const int goff = (tile + NBUF) * TT;
            #pragma unroll
            for (int q = 0; q < 4; q++) cp_async16(sbase[q] + soff, gbase[q] + goff);
            cp_commit();
        }
        buf ^= 1;
    }

    if (k == 1) { Fc = curc; Fs = cursum; Fp = curpc; }

    // Lazy vmax: only when the chunk has NO spikes. Rescan gmem.
    float vmax = -FLT_MAX;
    if (k == 0) {
        const float* g = vmem + (size_t)(traceBase + (tid & 15)) * T_DIM + c * CHUNK_T;
        #pragma unroll 1
        for (int j = 0; j < CHUNK_T; j++) vmax = fmaxf(vmax, g[j]);
    }

    // ---- chunk summaries to smem: [128][16] (block barrier; reuse ring area) ----
    __syncthreads();
    float* summ = sm;
    {
        float* w = summ + tid * 16;
        w[0]  = vmax;
        w[1]  = (float)(ft < 0 ? -1 : c * CHUNK_T + ft);
        w[2]  = (float)(c * CHUNK_T + last);
        w[3]  = (float)k;
        w[4]  = (float)Fc;   w[5]  = Fs;     w[6]  = (float)Fp;
        w[7]  = (float)Ic;   w[8]  = Is;     w[9]  = (float)Ip;
        w[10] = (float)curc; w[11] = cursum; w[12] = (float)curpc;
    }
    __syncthreads();

    // ---- merge 8 chunk summaries per trace (threads 0..15) ----
    float* red = sm + TPB * 16;
    float contrib = 0.0f;
    if (tid < TR_PB) {
        float vx = -FLT_MAX;
        int last_t = -1000000, nclust = 0;
        int   opc = -1, opp = 0;  float ops = 0.0f;            // open cluster
        int   bc = SENT, bp = 0;  float bs = 0.0f;             // best closed
        #pragma unroll
        for (int cc = 0; cc < S_CHUNKS; cc++) {
            const float* w = summ + (cc * TR_PB + tid) * 16;
            vx = fmaxf(vx, w[0]);
            const int kk = (int)w[3];
            if (kk == 0) continue;
            const int ftc = (int)w[1], ltc = (int)w[2];
            const int fC = (int)w[4], fP = (int)w[6];
            const int iC = (int)w[7], iP = (int)w[9];
            const int lC = (int)w[10], lP = (int)w[12];
            const float fS = w[5], iS = w[8], lS = w[11];

            if (opc >= 0 && (ftc - last_t) <= C_GAP) {
                const int   mc = opc + fC;
                const float ms = ops + fS;
                const int   mp = opp + fP;
                if (kk == 1) { opc = mc; ops = ms; opp = mp; }
                else {
                    if (mc < bc) { bc = mc; bs = ms; bp = mp; }
                    if (iC < bc) { bc = iC; bs = iS; bp = iP; }
                    opc = lC; ops = lS; opp = lP;
                    nclust += kk - 1;
                }
            } else {
                if (opc >= 0 && opc < bc) { bc = opc; bs = ops; bp = opp; }
                nclust += kk;
                if (kk == 1) { opc = fC; ops = fS; opp = fP; }
                else {
                    if (fC < bc) { bc = fC; bs = fS; bp = fP; }
                    if (iC < bc) { bc = iC; bs = iS; bp = iP; }
                    opc = lC; ops = lS; opp = lP;
                }
            }
            last_t = ltc;
        }
        if (opc >= 0 && opc < bc) { bc = opc; bs = ops; bp = opp; }

        const int trace = traceBase + tid;
        out[1 + trace] = (float)nclust;

        const int b = trace / N_DIM;
        const int n = trace - b * N_DIM;
        if (n == labels[b]) {
            if (nclust == 0) contrib = -vx;
        } else if (nclust > 0) {
            contrib = bs / fmaxf((float)bp, 1.0f);
        }
    }

    // ---- block tree reduction (128 threads; >=16 contribute 0) ----
    red[tid] = contrib;
    __syncthreads();
    #pragma unroll
    for (int off = TPB / 2; off > 0; off >>= 1) {
        if (tid < off) red[tid] += red[tid + off];
        __syncthreads();
    }
    if (tid == 0) {
        g_partial[blockIdx.x] = red[0];
        __threadfence();
        amLast = (atomicAdd(&g_count, 1u) == (unsigned)(gridDim.x - 1));
    }
    __syncthreads();

    if (amLast) {
        __threadfence();
        float x = 0.0f;
        #pragma unroll
        for (int j = 0; j < NBLOCKS / TPB; j++) x += g_partial[tid + TPB * j];
        red[tid] = x;
        __syncthreads();
        #pragma unroll
        for (int off = TPB / 2; off > 0; off >>= 1) {
            if (tid < off) red[tid] += red[tid + off];
            __syncthreads();
        }
        if (tid == 0) {
            out[0] = red[0];
            g_count = 0;                   // reset for next graph replay
        }
    }
}

extern "C" void kernel_launch(void* const* d_in, const int* in_sizes, int n_in,
                              void* d_out, int out_size)
{
    const float* vmem   = (const float*)d_in[0];
    // d_in[1] (vlastmem) unused by the forward computation.
    const int*   labels = (const int*)d_in[2];
    float*       out    = (float*)d_out;

    stca_fused<<<NBLOCKS, TPB>>>(vmem, labels, out);
}